// round 1
// baseline (speedup 1.0000x reference)
#include <cuda_runtime.h>
#include <cuda_bf16.h>
#include <math.h>

// Problem constants
#define BB   8
#define SS   512
#define DD   512
#define DFF  2048
#define NH   8
#define DHD  64
#define NT   (BB * SS)      // 4096 rows
#define NLAY 6
#define VOCAB 32000

// ---------------- device scratch (static globals: allocation-guard safe) ---
__device__ float g_x [NT * DD];
__device__ float g_y [NT * DD];
__device__ float g_q [NT * DD];
__device__ float g_k [NT * DD];
__device__ float g_v [NT * DD];
__device__ float g_a [NT * DD];
__device__ float g_t [NT * DD];
__device__ float g_ff[NT * DFF];

// ---------------- embed + positional encoding ------------------------------
__global__ void embed_kernel(const int* __restrict__ tok,
                             const float* __restrict__ emb,
                             float* __restrict__ out)
{
    int idx = blockIdx.x * blockDim.x + threadIdx.x;      // 0 .. NT*DD-1
    int row = idx >> 9;          // /512
    int d   = idx & 511;
    int s   = row & (SS - 1);    // row = b*SS + s
    int t   = tok[row];

    float freq = expf(-(float)(d & ~1) * (9.210340371976184f / 512.0f));
    float arg  = (float)s * freq;
    float pe   = (d & 1) ? cosf(arg) : sinf(arg);

    out[idx] = emb[(size_t)t * DD + d] * 22.62741699796952f + pe;
}

// ---------------- GEMM: C[M,N] = A[M,K] @ W[K,N] + bias, optional relu -----
// Tiles: 64x64, K-tile 16, 256 threads, 4x4 per-thread microtile.
__global__ __launch_bounds__(256)
void gemm64(const float* __restrict__ A, const float* __restrict__ W,
            const float* __restrict__ bias, float* __restrict__ C,
            int M, int N, int K, int relu)
{
    __shared__ float As[16][64];
    __shared__ float Bs[16][64];

    const int bm = blockIdx.y * 64;
    const int bn = blockIdx.x * 64;
    const int tid = threadIdx.x;
    const int tx = tid & 15;        // 0..15 -> N
    const int ty = tid >> 4;        // 0..15 -> M
    const int ar = tid >> 2;        // A row within tile
    const int ac = (tid & 3) * 4;   // A col (k) within tile
    const int br = tid >> 4;        // B row (k) within tile
    const int bc = (tid & 15) * 4;  // B col within tile

    float acc[4][4] = {};

    for (int k0 = 0; k0 < K; k0 += 16) {
        float4 av = *(const float4*)&A[(size_t)(bm + ar) * K + k0 + ac];
        float4 bv = *(const float4*)&W[(size_t)(k0 + br) * N + bn + bc];
        As[ac + 0][ar] = av.x;
        As[ac + 1][ar] = av.y;
        As[ac + 2][ar] = av.z;
        As[ac + 3][ar] = av.w;
        *(float4*)&Bs[br][bc] = bv;
        __syncthreads();

#pragma unroll
        for (int k = 0; k < 16; k++) {
            float4 a4 = *(const float4*)&As[k][ty * 4];
            float4 b4 = *(const float4*)&Bs[k][tx * 4];
            float a[4] = {a4.x, a4.y, a4.z, a4.w};
            float b[4] = {b4.x, b4.y, b4.z, b4.w};
#pragma unroll
            for (int i = 0; i < 4; i++)
#pragma unroll
                for (int j = 0; j < 4; j++)
                    acc[i][j] += a[i] * b[j];
        }
        __syncthreads();
    }

#pragma unroll
    for (int i = 0; i < 4; i++) {
        int row = bm + ty * 4 + i;
#pragma unroll
        for (int j = 0; j < 4; j++) {
            int col = bn + tx * 4 + j;
            float v = acc[i][j] + bias[col];
            if (relu) v = fmaxf(v, 0.0f);
            C[(size_t)row * N + col] = v;
        }
    }
}

// ---------------- fused attention -----------------------------------------
// One block = 8 query rows of one (batch, head). 128 threads.
// causal==0: key-pad mask from tok (src). causal==1: causal AND query-pad (tgt).
__global__ __launch_bounds__(128)
void attn_kernel(const float* __restrict__ Q, const float* __restrict__ Km,
                 const float* __restrict__ Vm, const int* __restrict__ tok,
                 int causal, float* __restrict__ O)
{
    const int q0 = blockIdx.x * 8;
    const int h  = blockIdx.y;
    const int b  = blockIdx.z;
    const int tid = threadIdx.x;

    __shared__ float qs[8][64];
    __shared__ float ks[64][65];
    __shared__ float sc[8][512];
    __shared__ int   tq[8];
    __shared__ int   kv[512];

    // load 8 query rows (head slice)
#pragma unroll
    for (int i = 0; i < 4; i++) {
        int e = tid + i * 128;
        int r = e >> 6, d = e & 63;
        qs[r][d] = Q[(size_t)(b * SS + q0 + r) * DD + h * 64 + d];
    }
    if (tid < 8) tq[tid] = tok[b * SS + q0 + tid];
    // key validity
#pragma unroll
    for (int i = 0; i < 4; i++) {
        int e = tid + i * 128;
        kv[e] = (tok[b * SS + e] != 0);
    }
    __syncthreads();

    // ---- scores ----
    for (int kt = 0; kt < SS; kt += 64) {
#pragma unroll
        for (int i = 0; i < 32; i++) {
            int e = tid + i * 128;
            int kr = e >> 6, d = e & 63;
            ks[kr][d] = Km[(size_t)(b * SS + kt + kr) * DD + h * 64 + d];
        }
        __syncthreads();

        const int kj = tid & 63;
#pragma unroll
        for (int i = 0; i < 4; i++) {
            int r = (tid >> 6) + 2 * i;     // covers rows 0..7
            float dot = 0.0f;
#pragma unroll
            for (int d = 0; d < 64; d++) dot += qs[r][d] * ks[kj][d];
            dot *= 0.125f;                  // 1/sqrt(64)
            int kg = kt + kj;
            bool valid;
            if (causal) valid = (tq[r] != 0) && (kg <= q0 + r);
            else        valid = (kv[kg] != 0);
            sc[r][kg] = valid ? dot : -1e9f;
        }
        __syncthreads();
    }

    // ---- softmax: 16-lane team per row ----
    {
        int r = tid >> 4, l = tid & 15;
        float mx = -3.4e38f;
        for (int c = 0; c < 32; c++) mx = fmaxf(mx, sc[r][l * 32 + c]);
        for (int s = 8; s; s >>= 1) mx = fmaxf(mx, __shfl_xor_sync(0xffffffffu, mx, s));
        float sum = 0.0f;
        for (int c = 0; c < 32; c++) {
            float e = expf(sc[r][l * 32 + c] - mx);
            sc[r][l * 32 + c] = e;
            sum += e;
        }
        for (int s = 8; s; s >>= 1) sum += __shfl_xor_sync(0xffffffffu, sum, s);
        float inv = 1.0f / sum;
        for (int c = 0; c < 32; c++) sc[r][l * 32 + c] *= inv;
    }
    __syncthreads();

    // ---- out = P @ V ----
    const int d    = tid & 63;
    const int part = tid >> 6;              // 0 -> rows 0..3, 1 -> rows 4..7
    float acc[4] = {0.f, 0.f, 0.f, 0.f};
    for (int kt = 0; kt < SS; kt += 64) {
        __syncthreads();                    // protect ks reuse
#pragma unroll
        for (int i = 0; i < 32; i++) {
            int e = tid + i * 128;
            int kr = e >> 6, dd = e & 63;
            ks[kr][dd] = Vm[(size_t)(b * SS + kt + kr) * DD + h * 64 + dd];
        }
        __syncthreads();
#pragma unroll
        for (int kj = 0; kj < 64; kj++) {
            float vv = ks[kj][d];
#pragma unroll
            for (int j = 0; j < 4; j++)
                acc[j] += sc[part * 4 + j][kt + kj] * vv;
        }
    }
#pragma unroll
    for (int j = 0; j < 4; j++)
        O[(size_t)(b * SS + q0 + part * 4 + j) * DD + h * 64 + d] = acc[j];
}

// ---------------- residual + LayerNorm: x = LN(t + x) * s + b --------------
__global__ __launch_bounds__(256)
void ln_res_kernel(const float* __restrict__ t, float* __restrict__ x,
                   const float* __restrict__ s, const float* __restrict__ b)
{
    const int row = blockIdx.x;
    const int tid = threadIdx.x;
    __shared__ float red[256];

    float u0 = t[(size_t)row * 512 + tid]       + x[(size_t)row * 512 + tid];
    float u1 = t[(size_t)row * 512 + tid + 256] + x[(size_t)row * 512 + tid + 256];

    red[tid] = u0 + u1;
    __syncthreads();
    for (int o = 128; o; o >>= 1) { if (tid < o) red[tid] += red[tid + o]; __syncthreads(); }
    float mean = red[0] * (1.0f / 512.0f);
    __syncthreads();

    float d0 = u0 - mean, d1 = u1 - mean;
    red[tid] = d0 * d0 + d1 * d1;
    __syncthreads();
    for (int o = 128; o; o >>= 1) { if (tid < o) red[tid] += red[tid + o]; __syncthreads(); }
    float inv = rsqrtf(red[0] * (1.0f / 512.0f) + 1e-5f);

    x[(size_t)row * 512 + tid]       = d0 * inv * s[tid]       + b[tid];
    x[(size_t)row * 512 + tid + 256] = d1 * inv * s[tid + 256] + b[tid + 256];
}

// ---------------- host orchestration ---------------------------------------
static inline void run_gemm(const float* A, const float* W, const float* bias,
                            float* C, int M, int N, int K, int relu)
{
    dim3 g(N / 64, M / 64);
    gemm64<<<g, 256>>>(A, W, bias, C, M, N, K, relu);
}

extern "C" void kernel_launch(void* const* d_in, const int* in_sizes, int n_in,
                              void* d_out, int out_size)
{
    const int*   src     = (const int*)  d_in[0];
    const int*   tgt     = (const int*)  d_in[1];
    const float* src_emb = (const float*)d_in[2];
    const float* tgt_emb = (const float*)d_in[3];
    const float* eaw     = (const float*)d_in[4];
    const float* eab     = (const float*)d_in[5];
    const float* els     = (const float*)d_in[6];
    const float* elb     = (const float*)d_in[7];
    const float* ef1     = (const float*)d_in[8];
    const float* eb1     = (const float*)d_in[9];
    const float* ef2     = (const float*)d_in[10];
    const float* eb2     = (const float*)d_in[11];
    const float* daw     = (const float*)d_in[12];
    const float* dab     = (const float*)d_in[13];
    const float* dls     = (const float*)d_in[14];
    const float* dlb     = (const float*)d_in[15];
    const float* df1     = (const float*)d_in[16];
    const float* db1     = (const float*)d_in[17];
    const float* df2     = (const float*)d_in[18];
    const float* db2     = (const float*)d_in[19];
    const float* fcw     = (const float*)d_in[20];
    const float* fcb     = (const float*)d_in[21];
    float*       out     = (float*)d_out;

    float *x, *y, *q, *k, *v, *a, *t, *ff;
    cudaGetSymbolAddress((void**)&x,  g_x);
    cudaGetSymbolAddress((void**)&y,  g_y);
    cudaGetSymbolAddress((void**)&q,  g_q);
    cudaGetSymbolAddress((void**)&k,  g_k);
    cudaGetSymbolAddress((void**)&v,  g_v);
    cudaGetSymbolAddress((void**)&a,  g_a);
    cudaGetSymbolAddress((void**)&t,  g_t);
    cudaGetSymbolAddress((void**)&ff, g_ff);

    const size_t WSZ = (size_t)DD * DD;     // 262144

    // embeddings + positional encoding
    embed_kernel<<<(NT * DD) / 256, 256>>>(src, src_emb, x);
    embed_kernel<<<(NT * DD) / 256, 256>>>(tgt, tgt_emb, y);

    dim3 ag(SS / 8, NH, BB);

    // ---------------- encoder ----------------
    for (int L = 0; L < NLAY; L++) {
        const float* W  = eaw + (size_t)L * 4 * WSZ;
        const float* Bz = eab + (size_t)L * 4 * DD;
        run_gemm(x, W + 0 * WSZ, Bz + 0 * DD, q, NT, DD, DD, 0);
        run_gemm(x, W + 1 * WSZ, Bz + 1 * DD, k, NT, DD, DD, 0);
        run_gemm(x, W + 2 * WSZ, Bz + 2 * DD, v, NT, DD, DD, 0);
        attn_kernel<<<ag, 128>>>(q, k, v, src, 0, a);
        run_gemm(a, W + 3 * WSZ, Bz + 3 * DD, t, NT, DD, DD, 0);
        ln_res_kernel<<<NT, 256>>>(t, x, els + (size_t)(L * 2 + 0) * DD, elb + (size_t)(L * 2 + 0) * DD);

        run_gemm(x,  ef1 + (size_t)L * DD * DFF, eb1 + (size_t)L * DFF, ff, NT, DFF, DD, 1);
        run_gemm(ff, ef2 + (size_t)L * DFF * DD, eb2 + (size_t)L * DD,  t,  NT, DD, DFF, 0);
        ln_res_kernel<<<NT, 256>>>(t, x, els + (size_t)(L * 2 + 1) * DD, elb + (size_t)(L * 2 + 1) * DD);
    }

    // ---------------- decoder ----------------
    for (int L = 0; L < NLAY; L++) {
        const float* W  = daw + (size_t)L * 8 * WSZ;
        const float* Bz = dab + (size_t)L * 8 * DD;

        // self-attention (causal + query-pad)
        run_gemm(y, W + 0 * WSZ, Bz + 0 * DD, q, NT, DD, DD, 0);
        run_gemm(y, W + 1 * WSZ, Bz + 1 * DD, k, NT, DD, DD, 0);
        run_gemm(y, W + 2 * WSZ, Bz + 2 * DD, v, NT, DD, DD, 0);
        attn_kernel<<<ag, 128>>>(q, k, v, tgt, 1, a);
        run_gemm(a, W + 3 * WSZ, Bz + 3 * DD, t, NT, DD, DD, 0);
        ln_res_kernel<<<NT, 256>>>(t, y, dls + (size_t)(L * 3 + 0) * DD, dlb + (size_t)(L * 3 + 0) * DD);

        // cross-attention (key-pad from src)
        run_gemm(y, W + 4 * WSZ, Bz + 4 * DD, q, NT, DD, DD, 0);
        run_gemm(x, W + 5 * WSZ, Bz + 5 * DD, k, NT, DD, DD, 0);
        run_gemm(x, W + 6 * WSZ, Bz + 6 * DD, v, NT, DD, DD, 0);
        attn_kernel<<<ag, 128>>>(q, k, v, src, 0, a);
        run_gemm(a, W + 7 * WSZ, Bz + 7 * DD, t, NT, DD, DD, 0);
        ln_res_kernel<<<NT, 256>>>(t, y, dls + (size_t)(L * 3 + 1) * DD, dlb + (size_t)(L * 3 + 1) * DD);

        // FFN
        run_gemm(y,  df1 + (size_t)L * DD * DFF, db1 + (size_t)L * DFF, ff, NT, DFF, DD, 1);
        run_gemm(ff, df2 + (size_t)L * DFF * DD, db2 + (size_t)L * DD,  t,  NT, DD, DFF, 0);
        ln_res_kernel<<<NT, 256>>>(t, y, dls + (size_t)(L * 3 + 2) * DD, dlb + (size_t)(L * 3 + 2) * DD);
    }

    // final projection to vocab
    run_gemm(y, fcw, fcb, out, NT, VOCAB, DD, 0);
}

// round 3
// speedup vs baseline: 1.5828x; 1.5828x over previous
#include <cuda_runtime.h>
#include <cuda_bf16.h>
#include <math.h>
#include <stdint.h>

// Problem constants
#define BB   8
#define SS   512
#define DD   512
#define DFF  2048
#define NH   8
#define NT   (BB * SS)      // 4096 rows
#define NLAY 6
#define VOCAB 32000

// ---------------- device scratch (static globals) --------------------------
__device__ float g_x [NT * DD];
__device__ float g_y [NT * DD];
__device__ float g_q [NT * DD];
__device__ float g_k [NT * DD];
__device__ float g_v [NT * DD];
__device__ float g_a [NT * DD];
__device__ float g_t [NT * DD];
__device__ float g_ff[NT * DFF];

// split-bf16 weights, transposed to [N,K]
#define W_TOTAL 60424192
__device__ __nv_bfloat16 g_wh[W_TOTAL];
__device__ __nv_bfloat16 g_wl[W_TOTAL];
// activation splits
__device__ __nv_bfloat16 g_ah[NT * DFF];
__device__ __nv_bfloat16 g_al[NT * DFF];
// encoder-output split (reused across all decoder layers)
__device__ __nv_bfloat16 g_xh[NT * DD];
__device__ __nv_bfloat16 g_xl[NT * DD];

// weight buffer offsets (elements)
#define OFF_EAW 0
#define OFF_DAW 6291456
#define OFF_EF1 18874368
#define OFF_EF2 25165824
#define OFF_DF1 31457280
#define OFF_DF2 37748736
#define OFF_FC  44040192
#define WSZ     262144          // 512*512

// ================= PTX helpers (baseline ISA: sm_80-era) ===================
__device__ __forceinline__ uint32_t s2u(const void* p) {
    uint32_t a;
    asm("{ .reg .u64 t; cvta.to.shared.u64 t, %1; cvt.u32.u64 %0, t; }"
        : "=r"(a) : "l"(p));
    return a;
}
__device__ __forceinline__ void cpa16(uint32_t s, const void* g) {
    asm volatile("cp.async.ca.shared.global [%0], [%1], 16;" :: "r"(s), "l"(g));
}
#define CP_COMMIT() asm volatile("cp.async.commit_group;" ::: "memory")
#define CP_WAIT(n)  asm volatile("cp.async.wait_group %0;" :: "n"(n) : "memory")

__device__ __forceinline__ void ldsm4(uint32_t* r, uint32_t addr) {
    asm volatile("ldmatrix.sync.aligned.m8n8.x4.shared.b16 {%0,%1,%2,%3}, [%4];"
        : "=r"(r[0]), "=r"(r[1]), "=r"(r[2]), "=r"(r[3]) : "r"(addr));
}
__device__ __forceinline__ void ldsm2(uint32_t* r, uint32_t addr) {
    asm volatile("ldmatrix.sync.aligned.m8n8.x2.shared.b16 {%0,%1}, [%2];"
        : "=r"(r[0]), "=r"(r[1]) : "r"(addr));
}
__device__ __forceinline__ void mma16816(float* d, const uint32_t* a, const uint32_t* b) {
    asm volatile(
        "mma.sync.aligned.m16n8k16.row.col.f32.bf16.bf16.f32 "
        "{%0,%1,%2,%3}, {%4,%5,%6,%7}, {%8,%9}, {%0,%1,%2,%3};"
        : "+f"(d[0]), "+f"(d[1]), "+f"(d[2]), "+f"(d[3])
        : "r"(a[0]), "r"(a[1]), "r"(a[2]), "r"(a[3]), "r"(b[0]), "r"(b[1]));
}

// SMEM geometry for gemm_tc
#define TS 40                         // padded row stride (bf16 elems)
#define MAT_BYTES (128 * TS * 2)      // 10240
#define STAGE_BYTES (4 * MAT_BYTES)   // 40960: Ah, Al, Bh, Bl
#define SM_TOTAL (2 * STAGE_BYTES)    // 81920

// ================= tensor-core GEMM (mma.sync) =============================
// C[M,N] = (Ah+Al)[M,K] @ (Bh+Bl)[N,K]^T + bias, optional relu.
// CTA: 128x128 tile, 256 threads (8 warps, 2M x 4N), K-tile 32, double-buffered.
__global__ __launch_bounds__(256)
void gemm_tc(const __nv_bfloat16* __restrict__ Ah, const __nv_bfloat16* __restrict__ Al,
             const __nv_bfloat16* __restrict__ Bh, const __nv_bfloat16* __restrict__ Bl,
             const float* __restrict__ bias, float* __restrict__ C,
             int M, int N, int K, int relu)
{
    extern __shared__ char smem[];
    const uint32_t sbase = s2u(smem);
    const int tid  = threadIdx.x;
    const int lane = tid & 31;
    const int wid  = tid >> 5;
    const int wm   = wid & 1;          // 0..1 -> M
    const int wn   = wid >> 1;         // 0..3 -> N
    const int bm   = blockIdx.y * 128;
    const int bn   = blockIdx.x * 128;

    float acc[16][4];
#pragma unroll
    for (int i = 0; i < 16; i++)
#pragma unroll
        for (int j = 0; j < 4; j++) acc[i][j] = 0.0f;

    // per-thread load coords: 512 16B-chunks per matrix per stage
    const int c0row = tid >> 2;            // 0..63   (+64 for second chunk)
    const int c0col = (tid & 3) * 8;       // 0,8,16,24

    const int nk = K >> 5;

    // ---- stage loader ----
    auto load_stage = [&](int stage, int k0) {
        uint32_t sb = sbase + stage * STAGE_BYTES;
#pragma unroll
        for (int i = 0; i < 2; i++) {
            int row = c0row + i * 64;
            uint32_t soff = (uint32_t)((row * TS + c0col) * 2);
            size_t ga = (size_t)(bm + row) * K + k0 + c0col;
            size_t gb = (size_t)(bn + row) * K + k0 + c0col;
            cpa16(sb + 0 * MAT_BYTES + soff, Ah + ga);
            cpa16(sb + 1 * MAT_BYTES + soff, Al + ga);
            cpa16(sb + 2 * MAT_BYTES + soff, Bh + gb);
            cpa16(sb + 3 * MAT_BYTES + soff, Bl + gb);
        }
    };

    load_stage(0, 0);
    CP_COMMIT();

    // ldmatrix lane addressing (element offsets)
    const int a_row_in = lane & 15;          // A: row within 16-row frag
    const int a_col_in = (lane >> 4) * 8;    // A: k-offset 0/8
    const int b_row_in = lane & 7;           // B: n within 8-row frag
    const int b_col_in = ((lane >> 3) & 1) * 8;  // B: k-offset 0/8

    for (int kt = 0; kt < nk; kt++) {
        if (kt + 1 < nk) {
            load_stage((kt + 1) & 1, (kt + 1) << 5);
            CP_COMMIT();
            CP_WAIT(1);
        } else {
            CP_WAIT(0);
        }
        __syncthreads();

        uint32_t sb = sbase + (kt & 1) * STAGE_BYTES;
#pragma unroll
        for (int ks = 0; ks < 2; ks++) {
            const int kb = ks * 16;
            uint32_t bh[4][2], bl[4][2];
#pragma unroll
            for (int ni = 0; ni < 4; ni++) {
                int nrow = wn * 32 + ni * 8 + b_row_in;
                uint32_t ad = sb + 2 * MAT_BYTES + (uint32_t)((nrow * TS + kb + b_col_in) * 2);
                ldsm2(bh[ni], ad);
                ldsm2(bl[ni], ad + MAT_BYTES);
            }
#pragma unroll
            for (int mi = 0; mi < 4; mi++) {
                int arow = wm * 64 + mi * 16 + a_row_in;
                uint32_t ad = sb + (uint32_t)((arow * TS + kb + a_col_in) * 2);
                uint32_t ah[4], al[4];
                ldsm4(ah, ad);
                ldsm4(al, ad + MAT_BYTES);
#pragma unroll
                for (int ni = 0; ni < 4; ni++) {
                    mma16816(acc[mi * 4 + ni], ah, bh[ni]);
                    mma16816(acc[mi * 4 + ni], ah, bl[ni]);
                    mma16816(acc[mi * 4 + ni], al, bh[ni]);
                }
            }
        }
        __syncthreads();
    }

    // ---- epilogue: direct writes (8B per thread per pair) ----
    const int er = lane >> 2;          // 0..7
    const int ec = (lane & 3) * 2;     // 0,2,4,6
#pragma unroll
    for (int mi = 0; mi < 4; mi++) {
#pragma unroll
        for (int ni = 0; ni < 4; ni++) {
            const float* a4 = acc[mi * 4 + ni];
            int m0 = bm + wm * 64 + mi * 16 + er;
            int n0 = bn + wn * 32 + ni * 8 + ec;
            float bz0 = bias[n0], bz1 = bias[n0 + 1];
            float v0 = a4[0] + bz0, v1 = a4[1] + bz1;
            float v2 = a4[2] + bz0, v3 = a4[3] + bz1;
            if (relu) {
                v0 = fmaxf(v0, 0.f); v1 = fmaxf(v1, 0.f);
                v2 = fmaxf(v2, 0.f); v3 = fmaxf(v3, 0.f);
            }
            *(float2*)&C[(size_t)m0 * N + n0]       = make_float2(v0, v1);
            *(float2*)&C[(size_t)(m0 + 8) * N + n0] = make_float2(v2, v3);
        }
    }
}

// ================= conversions =============================================
__global__ void acvt(const float* __restrict__ x, __nv_bfloat16* __restrict__ h,
                     __nv_bfloat16* __restrict__ l, int n)
{
    int i = blockIdx.x * 256 + threadIdx.x;
    if (i < n) {
        float v = x[i];
        __nv_bfloat16 hi = __float2bfloat16(v);
        h[i] = hi;
        l[i] = __float2bfloat16(v - __bfloat162float(hi));
    }
}

// weight fp32 [K,N] -> transposed hi/lo bf16 [N,K]; z selects matrix
__global__ void wconv(const float* __restrict__ W, __nv_bfloat16* __restrict__ oh,
                      __nv_bfloat16* __restrict__ ol, int K, int N)
{
    __shared__ float tile[32][33];
    size_t zoff = (size_t)blockIdx.z * K * N;
    const float* Wm = W + zoff;
    __nv_bfloat16* ohm = oh + zoff;
    __nv_bfloat16* olm = ol + zoff;

    int k0 = blockIdx.y * 32, n0 = blockIdx.x * 32;
    int tx = threadIdx.x, ty = threadIdx.y;
#pragma unroll
    for (int i = 0; i < 4; i++)
        tile[ty + i * 8][tx] = Wm[(size_t)(k0 + ty + i * 8) * N + n0 + tx];
    __syncthreads();
#pragma unroll
    for (int i = 0; i < 4; i++) {
        int n = n0 + ty + i * 8;
        int k = k0 + tx;
        float v = tile[tx][ty + i * 8];
        __nv_bfloat16 hi = __float2bfloat16(v);
        ohm[(size_t)n * K + k] = hi;
        olm[(size_t)n * K + k] = __float2bfloat16(v - __bfloat162float(hi));
    }
}

// ---------------- embed + positional encoding ------------------------------
__global__ void embed_kernel(const int* __restrict__ tok,
                             const float* __restrict__ emb,
                             float* __restrict__ out)
{
    int idx = blockIdx.x * blockDim.x + threadIdx.x;
    int row = idx >> 9;
    int d   = idx & 511;
    int s   = row & (SS - 1);
    int t   = tok[row];

    float freq = expf(-(float)(d & ~1) * (9.210340371976184f / 512.0f));
    float arg  = (float)s * freq;
    float pe   = (d & 1) ? cosf(arg) : sinf(arg);

    out[idx] = emb[(size_t)t * DD + d] * 22.62741699796952f + pe;
}

// ---------------- fused attention ------------------------------------------
__global__ __launch_bounds__(128)
void attn_kernel(const float* __restrict__ Q, const float* __restrict__ Km,
                 const float* __restrict__ Vm, const int* __restrict__ tok,
                 int causal, float* __restrict__ O)
{
    const int q0 = blockIdx.x * 8;
    const int h  = blockIdx.y;
    const int b  = blockIdx.z;
    const int tid = threadIdx.x;

    __shared__ float qs[8][64];
    __shared__ float ks[64][65];
    __shared__ float sc[8][512];
    __shared__ int   tq[8];
    __shared__ int   kv[512];

#pragma unroll
    for (int i = 0; i < 4; i++) {
        int e = tid + i * 128;
        int r = e >> 6, d = e & 63;
        qs[r][d] = Q[(size_t)(b * SS + q0 + r) * DD + h * 64 + d];
    }
    if (tid < 8) tq[tid] = tok[b * SS + q0 + tid];
#pragma unroll
    for (int i = 0; i < 4; i++) {
        int e = tid + i * 128;
        kv[e] = (tok[b * SS + e] != 0);
    }
    __syncthreads();

    for (int kt = 0; kt < SS; kt += 64) {
#pragma unroll
        for (int i = 0; i < 32; i++) {
            int e = tid + i * 128;
            int kr = e >> 6, d = e & 63;
            ks[kr][d] = Km[(size_t)(b * SS + kt + kr) * DD + h * 64 + d];
        }
        __syncthreads();

        const int kj = tid & 63;
#pragma unroll
        for (int i = 0; i < 4; i++) {
            int r = (tid >> 6) + 2 * i;
            float dot = 0.0f;
#pragma unroll
            for (int d = 0; d < 64; d++) dot += qs[r][d] * ks[kj][d];
            dot *= 0.125f;
            int kg = kt + kj;
            bool valid;
            if (causal) valid = (tq[r] != 0) && (kg <= q0 + r);
            else        valid = (kv[kg] != 0);
            sc[r][kg] = valid ? dot : -1e9f;
        }
        __syncthreads();
    }

    {
        int r = tid >> 4, l = tid & 15;
        float mx = -3.4e38f;
        for (int c = 0; c < 32; c++) mx = fmaxf(mx, sc[r][l * 32 + c]);
        for (int s = 8; s; s >>= 1) mx = fmaxf(mx, __shfl_xor_sync(0xffffffffu, mx, s));
        float sum = 0.0f;
        for (int c = 0; c < 32; c++) {
            float e = expf(sc[r][l * 32 + c] - mx);
            sc[r][l * 32 + c] = e;
            sum += e;
        }
        for (int s = 8; s; s >>= 1) sum += __shfl_xor_sync(0xffffffffu, sum, s);
        float inv = 1.0f / sum;
        for (int c = 0; c < 32; c++) sc[r][l * 32 + c] *= inv;
    }
    __syncthreads();

    const int d    = tid & 63;
    const int part = tid >> 6;
    float acc[4] = {0.f, 0.f, 0.f, 0.f};
    for (int kt = 0; kt < SS; kt += 64) {
        __syncthreads();
#pragma unroll
        for (int i = 0; i < 32; i++) {
            int e = tid + i * 128;
            int kr = e >> 6, dd = e & 63;
            ks[kr][dd] = Vm[(size_t)(b * SS + kt + kr) * DD + h * 64 + dd];
        }
        __syncthreads();
#pragma unroll
        for (int kj = 0; kj < 64; kj++) {
            float vv = ks[kj][d];
#pragma unroll
            for (int j = 0; j < 4; j++)
                acc[j] += sc[part * 4 + j][kt + kj] * vv;
        }
    }
#pragma unroll
    for (int j = 0; j < 4; j++)
        O[(size_t)(b * SS + q0 + part * 4 + j) * DD + h * 64 + d] = acc[j];
}

// ---------------- residual + LayerNorm -------------------------------------
__global__ __launch_bounds__(256)
void ln_res_kernel(const float* __restrict__ t, float* __restrict__ x,
                   const float* __restrict__ s, const float* __restrict__ b)
{
    const int row = blockIdx.x;
    const int tid = threadIdx.x;
    __shared__ float red[256];

    float u0 = t[(size_t)row * 512 + tid]       + x[(size_t)row * 512 + tid];
    float u1 = t[(size_t)row * 512 + tid + 256] + x[(size_t)row * 512 + tid + 256];

    red[tid] = u0 + u1;
    __syncthreads();
    for (int o = 128; o; o >>= 1) { if (tid < o) red[tid] += red[tid + o]; __syncthreads(); }
    float mean = red[0] * (1.0f / 512.0f);
    __syncthreads();

    float d0 = u0 - mean, d1 = u1 - mean;
    red[tid] = d0 * d0 + d1 * d1;
    __syncthreads();
    for (int o = 128; o; o >>= 1) { if (tid < o) red[tid] += red[tid + o]; __syncthreads(); }
    float inv = rsqrtf(red[0] * (1.0f / 512.0f) + 1e-5f);

    x[(size_t)row * 512 + tid]       = d0 * inv * s[tid]       + b[tid];
    x[(size_t)row * 512 + tid + 256] = d1 * inv * s[tid + 256] + b[tid + 256];
}

// ---------------- host orchestration ---------------------------------------
static __nv_bfloat16 *h_wh, *h_wl, *h_ah, *h_al, *h_xh, *h_xl;

static inline void run_gemm_tc(const __nv_bfloat16* Ah, const __nv_bfloat16* Al,
                               size_t woff, const float* bias, float* C,
                               int M, int N, int K, int relu)
{
    dim3 g(N / 128, M / 128);
    gemm_tc<<<g, 256, SM_TOTAL>>>(Ah, Al, h_wh + woff, h_wl + woff, bias, C, M, N, K, relu);
}

extern "C" void kernel_launch(void* const* d_in, const int* in_sizes, int n_in,
                              void* d_out, int out_size)
{
    const int*   src     = (const int*)  d_in[0];
    const int*   tgt     = (const int*)  d_in[1];
    const float* src_emb = (const float*)d_in[2];
    const float* tgt_emb = (const float*)d_in[3];
    const float* eaw     = (const float*)d_in[4];
    const float* eab     = (const float*)d_in[5];
    const float* els     = (const float*)d_in[6];
    const float* elb     = (const float*)d_in[7];
    const float* ef1     = (const float*)d_in[8];
    const float* eb1     = (const float*)d_in[9];
    const float* ef2     = (const float*)d_in[10];
    const float* eb2     = (const float*)d_in[11];
    const float* daw     = (const float*)d_in[12];
    const float* dab     = (const float*)d_in[13];
    const float* dls     = (const float*)d_in[14];
    const float* dlb     = (const float*)d_in[15];
    const float* df1     = (const float*)d_in[16];
    const float* db1     = (const float*)d_in[17];
    const float* df2     = (const float*)d_in[18];
    const float* db2     = (const float*)d_in[19];
    const float* fcw     = (const float*)d_in[20];
    const float* fcb     = (const float*)d_in[21];
    float*       out     = (float*)d_out;

    float *x, *y, *q, *k, *v, *a, *t, *ff;
    cudaGetSymbolAddress((void**)&x,  g_x);
    cudaGetSymbolAddress((void**)&y,  g_y);
    cudaGetSymbolAddress((void**)&q,  g_q);
    cudaGetSymbolAddress((void**)&k,  g_k);
    cudaGetSymbolAddress((void**)&v,  g_v);
    cudaGetSymbolAddress((void**)&a,  g_a);
    cudaGetSymbolAddress((void**)&t,  g_t);
    cudaGetSymbolAddress((void**)&ff, g_ff);
    cudaGetSymbolAddress((void**)&h_wh, g_wh);
    cudaGetSymbolAddress((void**)&h_wl, g_wl);
    cudaGetSymbolAddress((void**)&h_ah, g_ah);
    cudaGetSymbolAddress((void**)&h_al, g_al);
    cudaGetSymbolAddress((void**)&h_xh, g_xh);
    cudaGetSymbolAddress((void**)&h_xl, g_xl);

    cudaFuncSetAttribute(gemm_tc, cudaFuncAttributeMaxDynamicSharedMemorySize, SM_TOTAL);

    // ---- weight prep: transpose + split to bf16 hi/lo ----
    {
        dim3 b(32, 8);
        wconv<<<dim3(DD / 32, DD / 32, 24), b>>>(eaw, h_wh + OFF_EAW, h_wl + OFF_EAW, DD, DD);
        wconv<<<dim3(DD / 32, DD / 32, 48), b>>>(daw, h_wh + OFF_DAW, h_wl + OFF_DAW, DD, DD);
        wconv<<<dim3(DFF / 32, DD / 32, 6), b>>>(ef1, h_wh + OFF_EF1, h_wl + OFF_EF1, DD, DFF);
        wconv<<<dim3(DD / 32, DFF / 32, 6), b>>>(ef2, h_wh + OFF_EF2, h_wl + OFF_EF2, DFF, DD);
        wconv<<<dim3(DFF / 32, DD / 32, 6), b>>>(df1, h_wh + OFF_DF1, h_wl + OFF_DF1, DD, DFF);
        wconv<<<dim3(DD / 32, DFF / 32, 6), b>>>(df2, h_wh + OFF_DF2, h_wl + OFF_DF2, DFF, DD);
        wconv<<<dim3(VOCAB / 32, DD / 32, 1), b>>>(fcw, h_wh + OFF_FC, h_wl + OFF_FC, DD, VOCAB);
    }

    // embeddings + positional encoding
    embed_kernel<<<(NT * DD) / 256, 256>>>(src, src_emb, x);
    embed_kernel<<<(NT * DD) / 256, 256>>>(tgt, tgt_emb, y);

    dim3 ag(SS / 8, NH, BB);
    const int ND = NT * DD, NF = NT * DFF;

    // ---------------- encoder ----------------
    for (int L = 0; L < NLAY; L++) {
        size_t w0 = OFF_EAW + (size_t)(L * 4) * WSZ;
        const float* Bz = eab + (size_t)L * 4 * DD;

        acvt<<<ND / 256, 256>>>(x, h_ah, h_al, ND);
        run_gemm_tc(h_ah, h_al, w0 + 0 * WSZ, Bz + 0 * DD, q, NT, DD, DD, 0);
        run_gemm_tc(h_ah, h_al, w0 + 1 * WSZ, Bz + 1 * DD, k, NT, DD, DD, 0);
        run_gemm_tc(h_ah, h_al, w0 + 2 * WSZ, Bz + 2 * DD, v, NT, DD, DD, 0);
        attn_kernel<<<ag, 128>>>(q, k, v, src, 0, a);
        acvt<<<ND / 256, 256>>>(a, h_ah, h_al, ND);
        run_gemm_tc(h_ah, h_al, w0 + 3 * WSZ, Bz + 3 * DD, t, NT, DD, DD, 0);
        ln_res_kernel<<<NT, 256>>>(t, x, els + (size_t)(L * 2 + 0) * DD, elb + (size_t)(L * 2 + 0) * DD);

        acvt<<<ND / 256, 256>>>(x, h_ah, h_al, ND);
        run_gemm_tc(h_ah, h_al, OFF_EF1 + (size_t)L * DD * DFF, eb1 + (size_t)L * DFF, ff, NT, DFF, DD, 1);
        acvt<<<NF / 256, 256>>>(ff, h_ah, h_al, NF);
        run_gemm_tc(h_ah, h_al, OFF_EF2 + (size_t)L * DD * DFF, eb2 + (size_t)L * DD, t, NT, DD, DFF, 0);
        ln_res_kernel<<<NT, 256>>>(t, x, els + (size_t)(L * 2 + 1) * DD, elb + (size_t)(L * 2 + 1) * DD);
    }

    // encoder output split (reused by all decoder cross-attention K/V gemms)
    acvt<<<ND / 256, 256>>>(x, h_xh, h_xl, ND);

    // ---------------- decoder ----------------
    for (int L = 0; L < NLAY; L++) {
        size_t w0 = OFF_DAW + (size_t)(L * 8) * WSZ;
        const float* Bz = dab + (size_t)L * 8 * DD;

        // self-attention (causal + query-pad)
        acvt<<<ND / 256, 256>>>(y, h_ah, h_al, ND);
        run_gemm_tc(h_ah, h_al, w0 + 0 * WSZ, Bz + 0 * DD, q, NT, DD, DD, 0);
        run_gemm_tc(h_ah, h_al, w0 + 1 * WSZ, Bz + 1 * DD, k, NT, DD, DD, 0);
        run_gemm_tc(h_ah, h_al, w0 + 2 * WSZ, Bz + 2 * DD, v, NT, DD, DD, 0);
        attn_kernel<<<ag, 128>>>(q, k, v, tgt, 1, a);
        acvt<<<ND / 256, 256>>>(a, h_ah, h_al, ND);
        run_gemm_tc(h_ah, h_al, w0 + 3 * WSZ, Bz + 3 * DD, t, NT, DD, DD, 0);
        ln_res_kernel<<<NT, 256>>>(t, y, dls + (size_t)(L * 3 + 0) * DD, dlb + (size_t)(L * 3 + 0) * DD);

        // cross-attention (key-pad from src)
        acvt<<<ND / 256, 256>>>(y, h_ah, h_al, ND);
        run_gemm_tc(h_ah, h_al, w0 + 4 * WSZ, Bz + 4 * DD, q, NT, DD, DD, 0);
        run_gemm_tc(h_xh, h_xl, w0 + 5 * WSZ, Bz + 5 * DD, k, NT, DD, DD, 0);
        run_gemm_tc(h_xh, h_xl, w0 + 6 * WSZ, Bz + 6 * DD, v, NT, DD, DD, 0);
        attn_kernel<<<ag, 128>>>(q, k, v, src, 0, a);
        acvt<<<ND / 256, 256>>>(a, h_ah, h_al, ND);
        run_gemm_tc(h_ah, h_al, w0 + 7 * WSZ, Bz + 7 * DD, t, NT, DD, DD, 0);
        ln_res_kernel<<<NT, 256>>>(t, y, dls + (size_t)(L * 3 + 1) * DD, dlb + (size_t)(L * 3 + 1) * DD);

        // FFN
        acvt<<<ND / 256, 256>>>(y, h_ah, h_al, ND);
        run_gemm_tc(h_ah, h_al, OFF_DF1 + (size_t)L * DD * DFF, db1 + (size_t)L * DFF, ff, NT, DFF, DD, 1);
        acvt<<<NF / 256, 256>>>(ff, h_ah, h_al, NF);
        run_gemm_tc(h_ah, h_al, OFF_DF2 + (size_t)L * DD * DFF, db2 + (size_t)L * DD, t, NT, DD, DFF, 0);
        ln_res_kernel<<<NT, 256>>>(t, y, dls + (size_t)(L * 3 + 2) * DD, dlb + (size_t)(L * 3 + 2) * DD);
    }

    // final projection to vocab
    acvt<<<ND / 256, 256>>>(y, h_ah, h_al, ND);
    run_gemm_tc(h_ah, h_al, OFF_FC, fcb, out, NT, VOCAB, DD, 0);
}